// round 1
// baseline (speedup 1.0000x reference)
#include <cuda_runtime.h>
#include <math.h>

// Problem constants (fixed by reference)
#define T_TOT 2048   // B*S
#define E     512
#define NSEC  8
#define MMEM  2048
#define KD    32
#define VD    32
#define TOPK  4

// Scratch (device globals; no allocation allowed)
__device__ float g_xemb[T_TOT * E];            // 4 MB
__device__ float g_q[T_TOT * KD];
__device__ int   g_tidx[T_TOT * NSEC * TOPK];
__device__ float g_tw[T_TOT * NSEC * TOPK];

// ---------------------------------------------------------------------------
// top-4 insertion helpers (descending sorted lists in registers)
// ---------------------------------------------------------------------------
__device__ __forceinline__ void ins4(float s, int mi, float* v, int* ix) {
    // strict > : on tie keep earlier (lower m, since we scan ascending m)
    if (s > v[3]) {
        if (s > v[1]) {
            if (s > v[0]) {
                v[3]=v[2]; ix[3]=ix[2]; v[2]=v[1]; ix[2]=ix[1];
                v[1]=v[0]; ix[1]=ix[0]; v[0]=s; ix[0]=mi;
            } else {
                v[3]=v[2]; ix[3]=ix[2]; v[2]=v[1]; ix[2]=ix[1];
                v[1]=s; ix[1]=mi;
            }
        } else {
            if (s > v[2]) { v[3]=v[2]; ix[3]=ix[2]; v[2]=s; ix[2]=mi; }
            else          { v[3]=s; ix[3]=mi; }
        }
    }
}

__device__ __forceinline__ void ins4tie(float s, int mi, float* v, int* ix) {
    // candidates arrive unordered in m -> explicit (value, lower-index) tiebreak
    bool b3 = (s > v[3]) || (s == v[3] && mi < ix[3]);
    if (b3) {
        bool b1 = (s > v[1]) || (s == v[1] && mi < ix[1]);
        if (b1) {
            bool b0 = (s > v[0]) || (s == v[0] && mi < ix[0]);
            if (b0) {
                v[3]=v[2]; ix[3]=ix[2]; v[2]=v[1]; ix[2]=ix[1];
                v[1]=v[0]; ix[1]=ix[0]; v[0]=s; ix[0]=mi;
            } else {
                v[3]=v[2]; ix[3]=ix[2]; v[2]=v[1]; ix[2]=ix[1];
                v[1]=s; ix[1]=mi;
            }
        } else {
            bool b2 = (s > v[2]) || (s == v[2] && mi < ix[2]);
            if (b2) { v[3]=v[2]; ix[3]=ix[2]; v[2]=s; ix[2]=mi; }
            else    { v[3]=s; ix[3]=mi; }
        }
    }
}

// ---------------------------------------------------------------------------
// K1: embedding gather + sector softmax (output #2) + token query
// one block per token, 128 threads
// ---------------------------------------------------------------------------
__global__ __launch_bounds__(128) void k1_embed(
    const int* __restrict__ x, const float* __restrict__ emb,
    const float* __restrict__ skeys, const float* __restrict__ Wq,
    const float* __restrict__ bq, float* __restrict__ out_sector)
{
    int t = blockIdx.x;
    int tid = threadIdx.x;
    __shared__ float xs[E];
    __shared__ float ssc[NSEC];
    __shared__ float qred[128];

    int tok = x[t];
    const float* er = emb + (size_t)tok * E;
    for (int e = tid; e < E; e += 128) {
        float v = er[e];
        xs[e] = v;
        g_xemb[(size_t)t * E + e] = v;
    }
    __syncthreads();

    int wid = tid >> 5, lane = tid & 31;
    // sector scores: warp w handles sectors w and w+4
    for (int s = wid; s < NSEC; s += 4) {
        const float* kr = skeys + s * E;
        float acc = 0.f;
        for (int e = lane; e < E; e += 32) acc = fmaf(xs[e], kr[e], acc);
        #pragma unroll
        for (int o = 16; o > 0; o >>= 1) acc += __shfl_xor_sync(0xffffffffu, acc, o);
        if (lane == 0) ssc[s] = acc;
    }
    // token query: thread (d = tid&31, quarter = tid>>5)
    {
        int d = tid & 31, kq = tid >> 5;
        float acc = 0.f;
        int e0 = kq * 128;
        for (int e = e0; e < e0 + 128; e++) acc = fmaf(xs[e], Wq[e * KD + d], acc);
        qred[tid] = acc;
    }
    __syncthreads();
    if (tid < KD) {
        float v = qred[tid] + qred[tid + 32] + qred[tid + 64] + qred[tid + 96] + bq[tid];
        g_q[t * KD + tid] = v;
    }
    if (tid == 0) {
        float mx = ssc[0];
        #pragma unroll
        for (int i = 1; i < NSEC; i++) mx = fmaxf(mx, ssc[i]);
        float ex[NSEC]; float sum = 0.f;
        #pragma unroll
        for (int i = 0; i < NSEC; i++) { ex[i] = expf(ssc[i] - mx); sum += ex[i]; }
        float inv = 1.f / sum;
        #pragma unroll
        for (int i = 0; i < NSEC; i++) out_sector[t * NSEC + i] = ex[i] * inv;
    }
}

// ---------------------------------------------------------------------------
// K2: scores = x_emb @ memory_keys^T with fused per-(token,sector) top-4
// block = (16-token tile, sector). 128 threads, thread tile 4 tokens x 4 mems.
// Full softmax over M is mathematically unnecessary: renormalized top-k
// weights == softmax over the 4 raw top scores.
// ---------------------------------------------------------------------------
__global__ __launch_bounds__(128) void k2_topk(const float* __restrict__ mkeys)
{
    __shared__ float xs[E * 16];     // [e][t]  32 KB, resident for whole block
    __shared__ float ks[32 * 128];   // [e][m] key slice, 16 KB; reused for merge
    int tid = threadIdx.x;
    int mq = tid & 31, tq = tid >> 5;
    int t0 = blockIdx.x * 16;
    int n  = blockIdx.y;

    for (int i = tid; i < 16 * E; i += 128) {
        int t = i >> 9, e = i & (E - 1);
        xs[e * 16 + t] = g_xemb[(size_t)(t0 + t) * E + e];
    }

    float bv[4][4]; int bi[4][4];
    #pragma unroll
    for (int a = 0; a < 4; a++)
        #pragma unroll
        for (int j = 0; j < 4; j++) { bv[a][j] = -1e30f; bi[a][j] = 0x7fffffff; }

    const float* kbase = mkeys + (size_t)n * MMEM * E;
    for (int c = 0; c < MMEM / 128; c++) {
        float acc[4][4];
        #pragma unroll
        for (int a = 0; a < 4; a++)
            #pragma unroll
            for (int j = 0; j < 4; j++) acc[a][j] = 0.f;

        const float* krow = kbase + (size_t)(c * 128 + tid) * E;
        for (int kk = 0; kk < E; kk += 32) {
            __syncthreads();
            #pragma unroll
            for (int e4 = 0; e4 < 32; e4 += 4) {
                float4 v = *(const float4*)(krow + kk + e4);
                ks[(e4 + 0) * 128 + tid] = v.x;
                ks[(e4 + 1) * 128 + tid] = v.y;
                ks[(e4 + 2) * 128 + tid] = v.z;
                ks[(e4 + 3) * 128 + tid] = v.w;
            }
            __syncthreads();
            #pragma unroll
            for (int e = 0; e < 32; e++) {
                float4 xv = *(const float4*)(xs + (kk + e) * 16 + 4 * tq);
                float4 kv = *(const float4*)(ks + e * 128 + 4 * mq);
                acc[0][0] = fmaf(xv.x, kv.x, acc[0][0]);
                acc[0][1] = fmaf(xv.x, kv.y, acc[0][1]);
                acc[0][2] = fmaf(xv.x, kv.z, acc[0][2]);
                acc[0][3] = fmaf(xv.x, kv.w, acc[0][3]);
                acc[1][0] = fmaf(xv.y, kv.x, acc[1][0]);
                acc[1][1] = fmaf(xv.y, kv.y, acc[1][1]);
                acc[1][2] = fmaf(xv.y, kv.z, acc[1][2]);
                acc[1][3] = fmaf(xv.y, kv.w, acc[1][3]);
                acc[2][0] = fmaf(xv.z, kv.x, acc[2][0]);
                acc[2][1] = fmaf(xv.z, kv.y, acc[2][1]);
                acc[2][2] = fmaf(xv.z, kv.z, acc[2][2]);
                acc[2][3] = fmaf(xv.z, kv.w, acc[2][3]);
                acc[3][0] = fmaf(xv.w, kv.x, acc[3][0]);
                acc[3][1] = fmaf(xv.w, kv.y, acc[3][1]);
                acc[3][2] = fmaf(xv.w, kv.z, acc[3][2]);
                acc[3][3] = fmaf(xv.w, kv.w, acc[3][3]);
            }
        }
        #pragma unroll
        for (int a = 0; a < 4; a++)
            #pragma unroll
            for (int j = 0; j < 4; j++)
                ins4(acc[a][j], c * 128 + 4 * mq + j, bv[a], bi[a]);
    }

    // merge: 32 threads per token, 4 candidates each -> 128 candidates/token
    __syncthreads();
    float* cv = ks;                 // 2048 floats
    int*   ci = (int*)(ks + 2048);  // 2048 ints (fits exactly in ks region)
    #pragma unroll
    for (int a = 0; a < 4; a++) {
        int tl = 4 * tq + a;
        #pragma unroll
        for (int j = 0; j < 4; j++) {
            cv[tl * 128 + mq * 4 + j] = bv[a][j];
            ci[tl * 128 + mq * 4 + j] = bi[a][j];
        }
    }
    __syncthreads();
    if (tid < 16) {
        float v[4]; int ix[4];
        #pragma unroll
        for (int j = 0; j < 4; j++) { v[j] = -1e30f; ix[j] = 0x7fffffff; }
        for (int cnd = 0; cnd < 128; cnd++)
            ins4tie(cv[tid * 128 + cnd], ci[tid * 128 + cnd], v, ix);
        // softmax over the 4 raw scores == renormalized top-k softmax weights
        float e1 = expf(v[1] - v[0]);
        float e2 = expf(v[2] - v[0]);
        float e3 = expf(v[3] - v[0]);
        float inv = 1.f / (1.f + e1 + e2 + e3);
        int base = ((t0 + tid) * NSEC + n) * TOPK;
        g_tw[base + 0] = inv;
        g_tw[base + 1] = e1 * inv;
        g_tw[base + 2] = e2 * inv;
        g_tw[base + 3] = e3 * inv;
        g_tidx[base + 0] = ix[0];
        g_tidx[base + 1] = ix[1];
        g_tidx[base + 2] = ix[2];
        g_tidx[base + 3] = ix[3];
    }
}

// ---------------------------------------------------------------------------
// K3: gather knowledge, q@A, weight-combine, sector-combine, Wo proj,
//     residual + layernorm. One block per token, 256 threads (warp = sector).
// ---------------------------------------------------------------------------
__global__ __launch_bounds__(256) void k3_out(
    const float* __restrict__ knowledge, const float* __restrict__ Wo,
    const float* __restrict__ bo, const float* __restrict__ gamma,
    const float* __restrict__ beta, const float* __restrict__ sector_dist,
    float* __restrict__ out)
{
    int t = blockIdx.x;
    int tid = threadIdx.x;
    int wid = tid >> 5, lane = tid & 31;
    __shared__ float qs[KD];
    __shared__ float ctxs[NSEC * VD];
    __shared__ float finals[VD];
    __shared__ float red[16];
    __shared__ float mu_s, rstd_s;

    if (tid < KD) qs[tid] = g_q[t * KD + tid];
    __syncthreads();

    {   // warp `wid` handles sector n = wid; lane = output dim v
        int n = wid;
        int base = (t * NSEC + n) * TOPK;
        float acc = 0.f;
        #pragma unroll
        for (int k = 0; k < TOPK; k++) {
            int   mi = g_tidx[base + k];
            float w  = g_tw[base + k];
            const float* A = knowledge + (size_t)(n * MMEM + mi) * (KD * VD);
            float p = 0.f;
            #pragma unroll
            for (int d = 0; d < KD; d++) p = fmaf(qs[d], A[d * VD + lane], p);
            acc = fmaf(w, p, acc);
        }
        acc *= sector_dist[t * NSEC + n];
        ctxs[n * VD + lane] = acc;
    }
    __syncthreads();
    if (tid < VD) {
        float f = 0.f;
        #pragma unroll
        for (int n = 0; n < NSEC; n++) f += ctxs[n * VD + tid];
        finals[tid] = f;
    }
    __syncthreads();

    int e0 = tid, e1 = tid + 256;
    float p0 = bo[e0], p1 = bo[e1];
    #pragma unroll
    for (int v = 0; v < VD; v++) {
        float fv = finals[v];
        p0 = fmaf(fv, Wo[v * E + e0], p0);
        p1 = fmaf(fv, Wo[v * E + e1], p1);
    }
    float h0 = g_xemb[(size_t)t * E + e0] + p0;
    float h1 = g_xemb[(size_t)t * E + e1] + p1;

    float s = h0 + h1, sq = h0 * h0 + h1 * h1;
    #pragma unroll
    for (int o = 16; o > 0; o >>= 1) {
        s  += __shfl_xor_sync(0xffffffffu, s,  o);
        sq += __shfl_xor_sync(0xffffffffu, sq, o);
    }
    if (lane == 0) { red[wid] = s; red[8 + wid] = sq; }
    __syncthreads();
    if (tid == 0) {
        float S = 0.f, SQ = 0.f;
        #pragma unroll
        for (int i = 0; i < 8; i++) { S += red[i]; SQ += red[8 + i]; }
        float mu  = S * (1.f / E);
        float var = SQ * (1.f / E) - mu * mu;
        mu_s = mu;
        rstd_s = 1.f / sqrtf(var + 1e-5f);
    }
    __syncthreads();
    out[(size_t)t * E + e0] = (h0 - mu_s) * rstd_s * gamma[e0] + beta[e0];
    out[(size_t)t * E + e1] = (h1 - mu_s) * rstd_s * gamma[e1] + beta[e1];
}

// ---------------------------------------------------------------------------
extern "C" void kernel_launch(void* const* d_in, const int* in_sizes, int n_in,
                              void* d_out, int out_size)
{
    // top_k is a scalar input; detect whether the harness materialized it
    int off = (n_in >= 2 && in_sizes[1] == 1) ? 1 : 0;
    const int*   x     = (const int*)  d_in[0];
    const float* emb   = (const float*)d_in[1 + off];
    const float* skeys = (const float*)d_in[2 + off];
    const float* mkeys = (const float*)d_in[3 + off];
    const float* knw   = (const float*)d_in[4 + off];
    const float* Wq    = (const float*)d_in[5 + off];
    const float* bq    = (const float*)d_in[6 + off];
    const float* Wo    = (const float*)d_in[7 + off];
    const float* bo    = (const float*)d_in[8 + off];
    const float* gamma = (const float*)d_in[9 + off];
    const float* beta  = (const float*)d_in[10 + off];

    float* out    = (float*)d_out;
    float* sector = out + (size_t)T_TOT * E;   // tuple output #2

    k1_embed<<<T_TOT, 128>>>(x, emb, skeys, Wq, bq, sector);
    dim3 g2(T_TOT / 16, NSEC);
    k2_topk<<<g2, 128>>>(mkeys);
    k3_out<<<T_TOT, 256>>>(knw, Wo, bo, gamma, beta, sector, out);
}

// round 4
// speedup vs baseline: 4.8764x; 4.8764x over previous
#include <cuda_runtime.h>
#include <cuda_bf16.h>
#include <math.h>
#include <stdint.h>

// Problem constants
#define T_TOT 2048
#define E     512
#define NSEC  8
#define MMEM  2048
#define KD    32
#define VD    32
#define TOPK  4
#define NCAND 8

// ---------------------------------------------------------------------------
// Device-global scratch (no allocation allowed)
// ---------------------------------------------------------------------------
__device__ __align__(16) float         g_xemb[T_TOT * E];             // 4 MB
__device__ __align__(16) __nv_bfloat16 g_xemb_bf[T_TOT * E];          // 2 MB
__device__ __align__(16) __nv_bfloat16 g_mk_bf[NSEC * MMEM * E];      // 16.8 MB
__device__ __align__(16) float         g_scores[(size_t)NSEC * T_TOT * MMEM]; // 128 MB
__device__ float g_q[T_TOT * KD];
__device__ int   g_cand[T_TOT * NSEC * NCAND];
__device__ int   g_tidx[T_TOT * NSEC * TOPK];
__device__ float g_tw[T_TOT * NSEC * TOPK];

// ---------------------------------------------------------------------------
// PTX helpers
// ---------------------------------------------------------------------------
__device__ __forceinline__ uint32_t smem_to_u32(const void* p) {
    uint32_t a;
    asm("{ .reg .u64 t; cvta.to.shared.u64 t, %1; cvt.u32.u64 %0, t; }" : "=r"(a) : "l"(p));
    return a;
}
#define CP_ASYNC16(dst, src) \
    asm volatile("cp.async.cg.shared.global [%0], [%1], 16;" :: "r"(dst), "l"(src) : "memory")
#define CP_COMMIT() asm volatile("cp.async.commit_group;" ::: "memory")
#define CP_WAIT0()  asm volatile("cp.async.wait_group 0;" ::: "memory")

#define LDSM_X4(r0, r1, r2, r3, addr) \
    asm volatile("ldmatrix.sync.aligned.m8n8.x4.shared.b16 {%0,%1,%2,%3}, [%4];" \
        : "=r"(r0), "=r"(r1), "=r"(r2), "=r"(r3) : "r"(addr))

#define MMA16816(d, a0, a1, a2, a3, b0, b1) \
    asm volatile("mma.sync.aligned.m16n8k16.row.col.f32.bf16.bf16.f32 " \
        "{%0,%1,%2,%3}, {%4,%5,%6,%7}, {%8,%9}, {%0,%1,%2,%3};" \
        : "+f"((d)[0]), "+f"((d)[1]), "+f"((d)[2]), "+f"((d)[3]) \
        : "r"(a0), "r"(a1), "r"(a2), "r"(a3), "r"(b0), "r"(b1))

// ---------------------------------------------------------------------------
// top-k helpers
// ---------------------------------------------------------------------------
__device__ __forceinline__ void ins8(float s, int mi, float* v, int* ix) {
    if (s <= v[7]) return;
    v[7] = s; ix[7] = mi;
    #pragma unroll
    for (int j = 7; j > 0; j--) {
        if (v[j] > v[j - 1]) {
            float tv = v[j]; v[j] = v[j - 1]; v[j - 1] = tv;
            int   tt = ix[j]; ix[j] = ix[j - 1]; ix[j - 1] = tt;
        } else break;
    }
}
__device__ __forceinline__ void ins4tie(float s, int mi, float* v, int* ix) {
    bool b3 = (s > v[3]) || (s == v[3] && mi < ix[3]);
    if (b3) {
        bool b1 = (s > v[1]) || (s == v[1] && mi < ix[1]);
        if (b1) {
            bool b0 = (s > v[0]) || (s == v[0] && mi < ix[0]);
            if (b0) { v[3]=v[2]; ix[3]=ix[2]; v[2]=v[1]; ix[2]=ix[1]; v[1]=v[0]; ix[1]=ix[0]; v[0]=s; ix[0]=mi; }
            else    { v[3]=v[2]; ix[3]=ix[2]; v[2]=v[1]; ix[2]=ix[1]; v[1]=s; ix[1]=mi; }
        } else {
            bool b2 = (s > v[2]) || (s == v[2] && mi < ix[2]);
            if (b2) { v[3]=v[2]; ix[3]=ix[2]; v[2]=s; ix[2]=mi; }
            else    { v[3]=s; ix[3]=mi; }
        }
    }
}

// ---------------------------------------------------------------------------
// K0: memory_keys fp32 -> bf16
// ---------------------------------------------------------------------------
__global__ __launch_bounds__(256) void kconv(const float* __restrict__ mk) {
    size_t i = (size_t)blockIdx.x * 256 + threadIdx.x;
    const float4* s = (const float4*)mk + i * 2;
    float4 a = s[0], b = s[1];
    __nv_bfloat162* dst = (__nv_bfloat162*)&g_mk_bf[i * 8];
    dst[0] = __floats2bfloat162_rn(a.x, a.y);
    dst[1] = __floats2bfloat162_rn(a.z, a.w);
    dst[2] = __floats2bfloat162_rn(b.x, b.y);
    dst[3] = __floats2bfloat162_rn(b.z, b.w);
}

// ---------------------------------------------------------------------------
// K1: embedding gather (fp32 + bf16) + sector softmax + token query
// ---------------------------------------------------------------------------
__global__ __launch_bounds__(128) void k1_embed(
    const int* __restrict__ x, const float* __restrict__ emb,
    const float* __restrict__ skeys, const float* __restrict__ Wq,
    const float* __restrict__ bq, float* __restrict__ out_sector)
{
    int t = blockIdx.x;
    int tid = threadIdx.x;
    __shared__ float xs[E];
    __shared__ float ssc[NSEC];
    __shared__ float qred[128];

    int tok = x[t];
    const float* er = emb + (size_t)tok * E;
    for (int e = tid; e < E; e += 128) {
        float v = er[e];
        xs[e] = v;
        g_xemb[(size_t)t * E + e]    = v;
        g_xemb_bf[(size_t)t * E + e] = __float2bfloat16_rn(v);
    }
    __syncthreads();

    int wid = tid >> 5, lane = tid & 31;
    for (int s = wid; s < NSEC; s += 4) {
        const float* kr = skeys + s * E;
        float acc = 0.f;
        for (int e = lane; e < E; e += 32) acc = fmaf(xs[e], kr[e], acc);
        #pragma unroll
        for (int o = 16; o > 0; o >>= 1) acc += __shfl_xor_sync(0xffffffffu, acc, o);
        if (lane == 0) ssc[s] = acc;
    }
    {
        int d = tid & 31, kq = tid >> 5;
        float acc = 0.f;
        int e0 = kq * 128;
        for (int e = e0; e < e0 + 128; e++) acc = fmaf(xs[e], Wq[e * KD + d], acc);
        qred[tid] = acc;
    }
    __syncthreads();
    if (tid < KD) {
        g_q[t * KD + tid] = qred[tid] + qred[tid + 32] + qred[tid + 64] + qred[tid + 96] + bq[tid];
    }
    if (tid == 0) {
        float mx = ssc[0];
        #pragma unroll
        for (int i = 1; i < NSEC; i++) mx = fmaxf(mx, ssc[i]);
        float ex[NSEC]; float sum = 0.f;
        #pragma unroll
        for (int i = 0; i < NSEC; i++) { ex[i] = expf(ssc[i] - mx); sum += ex[i]; }
        float inv = 1.f / sum;
        #pragma unroll
        for (int i = 0; i < NSEC; i++) out_sector[t * NSEC + i] = ex[i] * inv;
    }
}

// ---------------------------------------------------------------------------
// K2: bf16 HMMA screen GEMM -> g_scores
//   grid (16 token tiles, 8 sectors), 256 threads (8 warps, 4x2).
//   CTA tile: 128 tokens x 128 mems, K = 512; warp tile 32x64.
//   A (128x512 bf16) smem-resident; B streamed 128x64 double-buffered cp.async.
// ---------------------------------------------------------------------------
#define SMEM_B_OFF 131072
#define K2_SMEM    (SMEM_B_OFF + 2 * 16384)

__global__ void __launch_bounds__(256, 1) k2_gemm() {
    extern __shared__ char smem[];
    uint32_t sa = smem_to_u32(smem);
    int tid = threadIdx.x;
    int lane = tid & 31, wid = tid >> 5;
    int wm = wid & 3, wn = wid >> 2;           // warp grid 4 (M) x 2 (N)
    int t0 = blockIdx.x * 128;
    int n  = blockIdx.y;

    // ---- A tile: 128 tokens x 512 bf16, rows 1024B, 16B-unit swizzle u^=(tok&7)
    for (int i = tid; i < 8192; i += 256) {
        uint32_t tok = (uint32_t)i >> 6, u = (uint32_t)i & 63;
        const void* src = g_xemb_bf + (size_t)(t0 + tok) * E + u * 8;
        uint32_t dst = sa + tok * 1024 + (((u & ~7u) | ((u ^ tok) & 7u)) << 4);
        CP_ASYNC16(dst, src);
    }
    // ---- B chunk 0
    const __nv_bfloat16* bbase = g_mk_bf + (size_t)n * MMEM * E;
    {
        for (int i = tid; i < 1024; i += 256) {
            uint32_t m = (uint32_t)i >> 3, u = (uint32_t)i & 7;
            const void* src = bbase + (size_t)m * E + u * 8;   // c=0, kc=0
            uint32_t dst = sa + SMEM_B_OFF + m * 128 + (((u ^ (m & 7u)) & 7u) << 4);
            CP_ASYNC16(dst, src);
        }
    }
    CP_COMMIT();

    float acc[2][8][4];
    #pragma unroll
    for (int mf = 0; mf < 2; mf++)
        #pragma unroll
        for (int nf = 0; nf < 8; nf++)
            #pragma unroll
            for (int r = 0; r < 4; r++) acc[mf][nf][r] = 0.f;

    // per-lane address components
    uint32_t aTok0 = (uint32_t)(wm * 32) + (uint32_t)(lane & 15);   // mf=0 token row
    uint32_t aHi   = (uint32_t)(lane >> 4);                         // extra k-unit
    uint32_t bMemB = (uint32_t)(wn * 64) + ((uint32_t)(lane >> 4) << 3) + (uint32_t)(lane & 7);
    uint32_t bKHi  = (uint32_t)((lane >> 3) & 1);

    for (int f = 0; f < 128; f++) {             // f = chunk*8 + kc
        int kc = f & 7, buf = f & 1, c = f >> 3;
        CP_WAIT0();
        __syncthreads();
        if (f + 1 < 128) {
            int c2 = (f + 1) >> 3, kc2 = (f + 1) & 7, buf2 = (f + 1) & 1;
            const __nv_bfloat16* bsrc = bbase + (size_t)(c2 * 128) * E + kc2 * 64;
            uint32_t db = sa + SMEM_B_OFF + (uint32_t)buf2 * 16384u;
            for (int i = tid; i < 1024; i += 256) {
                uint32_t m = (uint32_t)i >> 3, u = (uint32_t)i & 7;
                CP_ASYNC16(db + m * 128 + (((u ^ (m & 7u)) & 7u) << 4),
                           bsrc + (size_t)m * E + u * 8);
            }
            CP_COMMIT();
        }

        // load A fragments for this k-chunk: 2 m-frags x 4 k-steps
        uint32_t a[2][4][4];
        #pragma unroll
        for (int mf = 0; mf < 2; mf++) {
            uint32_t tok = aTok0 + (uint32_t)(mf * 16);
            uint32_t rowb = sa + tok * 1024;
            #pragma unroll
            for (int ks = 0; ks < 4; ks++) {
                uint32_t u = (uint32_t)(kc * 8 + ks * 2) + aHi;
                uint32_t addr = rowb + (((u & ~7u) | ((u ^ tok) & 7u)) << 4);
                LDSM_X4(a[mf][ks][0], a[mf][ks][1], a[mf][ks][2], a[mf][ks][3], addr);
            }
        }
        uint32_t bB = sa + SMEM_B_OFF + (uint32_t)buf * 16384u;
        #pragma unroll
        for (int np = 0; np < 4; np++) {
            uint32_t mem = bMemB + (uint32_t)(np * 16);
            uint32_t rowb = bB + mem * 128;
            #pragma unroll
            for (int ks = 0; ks < 4; ks++) {
                uint32_t b0, b1, b2, b3;
                uint32_t u = (uint32_t)(ks * 2) + bKHi;
                uint32_t addr = rowb + (((u ^ (mem & 7u)) & 7u) << 4);
                LDSM_X4(b0, b1, b2, b3, addr);
                #pragma unroll
                for (int mf = 0; mf < 2; mf++) {
                    MMA16816(acc[mf][np * 2 + 0], a[mf][ks][0], a[mf][ks][1], a[mf][ks][2], a[mf][ks][3], b0, b1);
                    MMA16816(acc[mf][np * 2 + 1], a[mf][ks][0], a[mf][ks][1], a[mf][ks][2], a[mf][ks][3], b2, b3);
                }
            }
        }

        if (kc == 7) {  // epilogue: write 128x128 scores for chunk c
            #pragma unroll
            for (int mf = 0; mf < 2; mf++) {
                int row = t0 + wm * 32 + mf * 16 + (lane >> 2);
                #pragma unroll
                for (int nf = 0; nf < 8; nf++) {
                    int col = c * 128 + wn * 64 + nf * 8 + ((lane & 3) << 1);
                    float* p0 = g_scores + ((size_t)n * T_TOT + row) * MMEM + col;
                    *(float2*)p0 = make_float2(acc[mf][nf][0], acc[mf][nf][1]);
                    *(float2*)(p0 + 8 * MMEM) = make_float2(acc[mf][nf][2], acc[mf][nf][3]);
                    acc[mf][nf][0] = acc[mf][nf][1] = acc[mf][nf][2] = acc[mf][nf][3] = 0.f;
                }
            }
        }
    }
}

// ---------------------------------------------------------------------------
// K2b: top-8 scan over scores. warp per (token, sector).
// ---------------------------------------------------------------------------
#define CE(a, b) do { if (v[a] < v[b]) { float tv=v[a]; v[a]=v[b]; v[b]=tv; int ti_=ix[a]; ix[a]=ix[b]; ix[b]=ti_; } } while (0)

__global__ __launch_bounds__(128) void k2b_scan() {
    int tid = threadIdx.x, lane = tid & 31, w = tid >> 5;
    int t = blockIdx.x * 4 + w;
    int n = blockIdx.y;
    const float4* row = (const float4*)(g_scores + ((size_t)n * T_TOT + t) * MMEM);

    float v[8]; int ix[8];
    #pragma unroll
    for (int j = 0; j < 8; j++) { v[j] = -1e30f; ix[j] = 0x7fffffff; }

    #pragma unroll 4
    for (int i = 0; i < 16; i++) {
        float4 val = row[i * 32 + lane];
        int mb = (i * 32 + lane) * 4;
        ins8(val.x, mb + 0, v, ix);
        ins8(val.y, mb + 1, v, ix);
        ins8(val.z, mb + 2, v, ix);
        ins8(val.w, mb + 3, v, ix);
    }
    // butterfly merge of sorted-desc top8 lists (bitonic pair-max + clean)
    #pragma unroll
    for (int o = 1; o < 32; o <<= 1) {
        float pv[8]; int pi[8];
        #pragma unroll
        for (int j = 0; j < 8; j++) {
            pv[j] = __shfl_xor_sync(0xffffffffu, v[j], o);
            pi[j] = __shfl_xor_sync(0xffffffffu, ix[j], o);
        }
        #pragma unroll
        for (int j = 0; j < 8; j++) {
            if (v[j] < pv[7 - j]) { v[j] = pv[7 - j]; ix[j] = pi[7 - j]; }
        }
        CE(0,4); CE(1,5); CE(2,6); CE(3,7);
        CE(0,2); CE(1,3); CE(4,6); CE(5,7);
        CE(0,1); CE(2,3); CE(4,5); CE(6,7);
    }
    if (lane == 0) {
        int base = (t * NSEC + n) * NCAND;
        #pragma unroll
        for (int j = 0; j < 8; j++) g_cand[base + j] = ix[j];
    }
}

// ---------------------------------------------------------------------------
// K2c: exact fp32 rescore of 8 candidates -> exact top-4 + softmax weights
// ---------------------------------------------------------------------------
__global__ __launch_bounds__(256) void k2c_rescore(const float* __restrict__ mkeys) {
    int t = blockIdx.x;
    int tid = threadIdx.x, wid = tid >> 5, lane = tid & 31;
    __shared__ float xs[E];
    for (int e = tid; e < E; e += 256) xs[e] = g_xemb[(size_t)t * E + e];
    __syncthreads();

    int n  = wid;
    int cb = (t * NSEC + n) * NCAND;
    float sc[NCAND]; int id[NCAND];
    #pragma unroll
    for (int j = 0; j < NCAND; j++) {
        int mi = g_cand[cb + j];
        const float* kr = mkeys + ((size_t)n * MMEM + mi) * E;
        float acc = 0.f;
        for (int e = lane; e < E; e += 32) acc = fmaf(xs[e], kr[e], acc);
        #pragma unroll
        for (int o = 16; o > 0; o >>= 1) acc += __shfl_xor_sync(0xffffffffu, acc, o);
        sc[j] = acc; id[j] = mi;
    }
    if (lane == 0) {
        float v[4]; int ix[4];
        #pragma unroll
        for (int j = 0; j < 4; j++) { v[j] = -1e30f; ix[j] = 0x7fffffff; }
        #pragma unroll
        for (int j = 0; j < NCAND; j++) ins4tie(sc[j], id[j], v, ix);
        float e1 = expf(v[1] - v[0]);
        float e2 = expf(v[2] - v[0]);
        float e3 = expf(v[3] - v[0]);
        float inv = 1.f / (1.f + e1 + e2 + e3);
        int ob = (t * NSEC + n) * TOPK;
        g_tw[ob + 0] = inv;      g_tw[ob + 1] = e1 * inv;
        g_tw[ob + 2] = e2 * inv; g_tw[ob + 3] = e3 * inv;
        g_tidx[ob + 0] = ix[0];  g_tidx[ob + 1] = ix[1];
        g_tidx[ob + 2] = ix[2];  g_tidx[ob + 3] = ix[3];
    }
}

// ---------------------------------------------------------------------------
// K3: knowledge gather + combine + Wo proj + residual + layernorm
// ---------------------------------------------------------------------------
__global__ __launch_bounds__(256) void k3_out(
    const float* __restrict__ knowledge, const float* __restrict__ Wo,
    const float* __restrict__ bo, const float* __restrict__ gamma,
    const float* __restrict__ beta, const float* __restrict__ sector_dist,
    float* __restrict__ out)
{
    int t = blockIdx.x;
    int tid = threadIdx.x;
    int wid = tid >> 5, lane = tid & 31;
    __shared__ float qs[KD];
    __shared__ float ctxs[NSEC * VD];
    __shared__ float finals[VD];
    __shared__ float red[16];
    __shared__ float mu_s, rstd_s;

    if (tid < KD) qs[tid] = g_q[t * KD + tid];
    __syncthreads();

    {
        int n = wid;
        int base = (t * NSEC + n) * TOPK;
        float acc = 0.f;
        #pragma unroll
        for (int k = 0; k < TOPK; k++) {
            int   mi = g_tidx[base + k];
            float w  = g_tw[base + k];
            const float* A = knowledge + (size_t)(n * MMEM + mi) * (KD * VD);
            float p = 0.f;
            #pragma unroll
            for (int d = 0; d < KD; d++) p = fmaf(qs[d], A[d * VD + lane], p);
            acc = fmaf(w, p, acc);
        }
        acc *= sector_dist[t * NSEC + n];
        ctxs[n * VD + lane] = acc;
    }
    __syncthreads();
    if (tid < VD) {
        float f = 0.f;
        #pragma unroll
        for (int n = 0; n < NSEC; n++) f += ctxs[n * VD + tid];
        finals[tid] = f;
    }
    __syncthreads();

    int e0 = tid, e1 = tid + 256;
    float p0 = bo[e0], p1 = bo[e1];
    #pragma unroll
    for (int v = 0; v < VD; v++) {
        float fv = finals[v];
        p0 = fmaf(fv, Wo[v * E + e0], p0);
        p1 = fmaf(fv, Wo[v * E + e1], p1);
    }
    float h0 = g_xemb[(size_t)t * E + e0] + p0;
    float h1 = g_xemb[(size_t)t * E + e1] + p1;

    float s = h0 + h1, sq = h0 * h0 + h1 * h1;
    #pragma unroll
    for (int o = 16; o > 0; o >>= 1) {
        s  += __shfl_xor_sync(0xffffffffu, s,  o);
        sq += __shfl_xor_sync(0xffffffffu, sq, o);
    }
    if (lane == 0) { red[wid] = s; red[8 + wid] = sq; }
    __syncthreads();
    if (tid == 0) {
        float S = 0.f, SQ = 0.f;
        #pragma unroll
        for (int i = 0; i < 8; i++) { S += red[i]; SQ += red[8 + i]; }
        float mu  = S * (1.f / E);
        float var = SQ * (1.f / E) - mu * mu;
        mu_s = mu;
        rstd_s = 1.f / sqrtf(var + 1e-5f);
    }
    __syncthreads();
    out[(size_t)t * E + e0] = (h0 - mu_s) * rstd_s * gamma[e0] + beta[e0];
    out[(size_t)t * E + e1] = (h1 - mu_s) * rstd_s * gamma[e1] + beta[e1];
}

// ---------------------------------------------------------------------------
extern "C" void kernel_launch(void* const* d_in, const int* in_sizes, int n_in,
                              void* d_out, int out_size)
{
    int off = (n_in >= 2 && in_sizes[1] == 1) ? 1 : 0;
    const int*   x     = (const int*)  d_in[0];
    const float* emb   = (const float*)d_in[1 + off];
    const float* skeys = (const float*)d_in[2 + off];
    const float* mkeys = (const float*)d_in[3 + off];
    const float* knw   = (const float*)d_in[4 + off];
    const float* Wq    = (const float*)d_in[5 + off];
    const float* bq    = (const float*)d_in[6 + off];
    const float* Wo    = (const float*)d_in[7 + off];
    const float* bo    = (const float*)d_in[8 + off];
    const float* gamma = (const float*)d_in[9 + off];
    const float* beta  = (const float*)d_in[10 + off];

    float* out    = (float*)d_out;
    float* sector = out + (size_t)T_TOT * E;

    (void)cudaFuncSetAttribute(k2_gemm, cudaFuncAttributeMaxDynamicSharedMemorySize, K2_SMEM);

    kconv<<<4096, 256>>>(mkeys);
    k1_embed<<<T_TOT, 128>>>(x, emb, skeys, Wq, bq, sector);
    dim3 g2(T_TOT / 128, NSEC);
    k2_gemm<<<g2, 256, K2_SMEM>>>();
    dim3 g2b(T_TOT / 4, NSEC);
    k2b_scan<<<g2b, 128>>>();
    k2c_rescore<<<T_TOT, 256>>>(mkeys);
    k3_out<<<T_TOT, 256>>>(knw, Wo, bo, gamma, beta, sector, out);
}

// round 5
// speedup vs baseline: 6.1360x; 1.2583x over previous
#include <cuda_runtime.h>
#include <cuda_bf16.h>
#include <math.h>
#include <stdint.h>

// Problem constants
#define T_TOT 2048
#define E     512
#define NSEC  8
#define MMEM  2048
#define KD    32
#define VD    32
#define TOPK  4
#define NCAND 8

// ---------------------------------------------------------------------------
// Device-global scratch (no allocation allowed)
// ---------------------------------------------------------------------------
__device__ __align__(16) float         g_xemb[T_TOT * E];             // 4 MB
__device__ __align__(16) __nv_bfloat16 g_xemb_bf[T_TOT * E];          // 2 MB
__device__ __align__(16) __nv_bfloat16 g_mk_bf[NSEC * MMEM * E];      // 16.8 MB
__device__ float g_q[T_TOT * KD];
__device__ int   g_cand[T_TOT * NSEC * NCAND];
__device__ int   g_tidx[T_TOT * NSEC * TOPK];
__device__ float g_tw[T_TOT * NSEC * TOPK];

// ---------------------------------------------------------------------------
// PTX helpers
// ---------------------------------------------------------------------------
__device__ __forceinline__ uint32_t smem_to_u32(const void* p) {
    uint32_t a;
    asm("{ .reg .u64 t; cvta.to.shared.u64 t, %1; cvt.u32.u64 %0, t; }" : "=r"(a) : "l"(p));
    return a;
}
#define CP_ASYNC16(dst, src) \
    asm volatile("cp.async.cg.shared.global [%0], [%1], 16;" :: "r"(dst), "l"(src) : "memory")
#define CP_COMMIT() asm volatile("cp.async.commit_group;" ::: "memory")
#define CP_WAIT0()  asm volatile("cp.async.wait_group 0;" ::: "memory")

#define LDSM_X4(r0, r1, r2, r3, addr) \
    asm volatile("ldmatrix.sync.aligned.m8n8.x4.shared.b16 {%0,%1,%2,%3}, [%4];" \
        : "=r"(r0), "=r"(r1), "=r"(r2), "=r"(r3) : "r"(addr))

#define MMA16816(d, a0, a1, a2, a3, b0, b1) \
    asm volatile("mma.sync.aligned.m16n8k16.row.col.f32.bf16.bf16.f32 " \
        "{%0,%1,%2,%3}, {%4,%5,%6,%7}, {%8,%9}, {%0,%1,%2,%3};" \
        : "+f"((d)[0]), "+f"((d)[1]), "+f"((d)[2]), "+f"((d)[3]) \
        : "r"(a0), "r"(a1), "r"(a2), "r"(a3), "r"(b0), "r"(b1))

// ---------------------------------------------------------------------------
// top-k helpers
// ---------------------------------------------------------------------------
__device__ __forceinline__ void ins5(float s, int mi, float* v, int* ix) {
    if (s <= v[4]) return;
    v[4] = s; ix[4] = mi;
    #pragma unroll
    for (int j = 4; j > 0; j--) {
        if (v[j] > v[j - 1]) {
            float tv = v[j]; v[j] = v[j - 1]; v[j - 1] = tv;
            int   tt = ix[j]; ix[j] = ix[j - 1]; ix[j - 1] = tt;
        } else break;
    }
}
// pair fast-filter: only enter insert path if either value can make the list
__device__ __forceinline__ void upd5(float* v, int* ix, float x0, int c0, float x1, int c1) {
    if (fmaxf(x0, x1) > v[4]) { ins5(x0, c0, v, ix); ins5(x1, c1, v, ix); }
}
__device__ __forceinline__ void ins8(float s, int mi, float* v, int* ix) {
    if (s <= v[7]) return;
    v[7] = s; ix[7] = mi;
    #pragma unroll
    for (int j = 7; j > 0; j--) {
        if (v[j] > v[j - 1]) {
            float tv = v[j]; v[j] = v[j - 1]; v[j - 1] = tv;
            int   tt = ix[j]; ix[j] = ix[j - 1]; ix[j - 1] = tt;
        } else break;
    }
}
__device__ __forceinline__ void ins4tie(float s, int mi, float* v, int* ix) {
    bool b3 = (s > v[3]) || (s == v[3] && mi < ix[3]);
    if (b3) {
        bool b1 = (s > v[1]) || (s == v[1] && mi < ix[1]);
        if (b1) {
            bool b0 = (s > v[0]) || (s == v[0] && mi < ix[0]);
            if (b0) { v[3]=v[2]; ix[3]=ix[2]; v[2]=v[1]; ix[2]=ix[1]; v[1]=v[0]; ix[1]=ix[0]; v[0]=s; ix[0]=mi; }
            else    { v[3]=v[2]; ix[3]=ix[2]; v[2]=v[1]; ix[2]=ix[1]; v[1]=s; ix[1]=mi; }
        } else {
            bool b2 = (s > v[2]) || (s == v[2] && mi < ix[2]);
            if (b2) { v[3]=v[2]; ix[3]=ix[2]; v[2]=s; ix[2]=mi; }
            else    { v[3]=s; ix[3]=mi; }
        }
    }
}

// ---------------------------------------------------------------------------
// K0: memory_keys fp32 -> bf16
// ---------------------------------------------------------------------------
__global__ __launch_bounds__(256) void kconv(const float* __restrict__ mk) {
    size_t i = (size_t)blockIdx.x * 256 + threadIdx.x;
    const float4* s = (const float4*)mk + i * 2;
    float4 a = s[0], b = s[1];
    __nv_bfloat162* dst = (__nv_bfloat162*)&g_mk_bf[i * 8];
    dst[0] = __floats2bfloat162_rn(a.x, a.y);
    dst[1] = __floats2bfloat162_rn(a.z, a.w);
    dst[2] = __floats2bfloat162_rn(b.x, b.y);
    dst[3] = __floats2bfloat162_rn(b.z, b.w);
}

// ---------------------------------------------------------------------------
// K1: embedding gather (fp32 + bf16) + sector softmax + token query
// ---------------------------------------------------------------------------
__global__ __launch_bounds__(128) void k1_embed(
    const int* __restrict__ x, const float* __restrict__ emb,
    const float* __restrict__ skeys, const float* __restrict__ Wq,
    const float* __restrict__ bq, float* __restrict__ out_sector)
{
    int t = blockIdx.x;
    int tid = threadIdx.x;
    __shared__ float xs[E];
    __shared__ float ssc[NSEC];
    __shared__ float qred[128];

    int tok = x[t];
    const float* er = emb + (size_t)tok * E;
    for (int e = tid; e < E; e += 128) {
        float v = er[e];
        xs[e] = v;
        g_xemb[(size_t)t * E + e]    = v;
        g_xemb_bf[(size_t)t * E + e] = __float2bfloat16_rn(v);
    }
    __syncthreads();

    int wid = tid >> 5, lane = tid & 31;
    for (int s = wid; s < NSEC; s += 4) {
        const float* kr = skeys + s * E;
        float acc = 0.f;
        for (int e = lane; e < E; e += 32) acc = fmaf(xs[e], kr[e], acc);
        #pragma unroll
        for (int o = 16; o > 0; o >>= 1) acc += __shfl_xor_sync(0xffffffffu, acc, o);
        if (lane == 0) ssc[s] = acc;
    }
    {
        int d = tid & 31, kq = tid >> 5;
        float acc = 0.f;
        int e0 = kq * 128;
        for (int e = e0; e < e0 + 128; e++) acc = fmaf(xs[e], Wq[e * KD + d], acc);
        qred[tid] = acc;
    }
    __syncthreads();
    if (tid < KD) {
        g_q[t * KD + tid] = qred[tid] + qred[tid + 32] + qred[tid + 64] + qred[tid + 96] + bq[tid];
    }
    if (tid == 0) {
        float mx = ssc[0];
        #pragma unroll
        for (int i = 1; i < NSEC; i++) mx = fmaxf(mx, ssc[i]);
        float ex[NSEC]; float sum = 0.f;
        #pragma unroll
        for (int i = 0; i < NSEC; i++) { ex[i] = expf(ssc[i] - mx); sum += ex[i]; }
        float inv = 1.f / sum;
        #pragma unroll
        for (int i = 0; i < NSEC; i++) out_sector[t * NSEC + i] = ex[i] * inv;
    }
}

// ---------------------------------------------------------------------------
// K2: bf16 HMMA screen GEMM with FUSED per-thread top-5 screening.
//   grid (16 token tiles, 8 sectors), 256 threads (8 warps, 4x2).
//   CTA tile: 128 tokens x 128 mems per chunk, K = 512, 16 chunks.
//   No score materialization: each thread keeps top-5 per owned row (4 rows);
//   union of 8 owning threads' top-5 (40 cand) provably contains the
//   screen-space top-4; final per-row top-8 by screen value -> g_cand.
// ---------------------------------------------------------------------------
#define SMEM_B_OFF 131072
#define K2_SMEM    (SMEM_B_OFF + 2 * 16384)

__global__ void __launch_bounds__(256, 1) k2_gemm() {
    extern __shared__ char smem[];
    uint32_t sa = smem_to_u32(smem);
    int tid = threadIdx.x;
    int lane = tid & 31, wid = tid >> 5;
    int wm = wid & 3, wn = wid >> 2;           // warp grid 4 (M) x 2 (N)
    int t0 = blockIdx.x * 128;
    int n  = blockIdx.y;

    // ---- A tile: 128 tokens x 512 bf16, rows 1024B, 16B-unit swizzle u^=(tok&7)
    for (int i = tid; i < 8192; i += 256) {
        uint32_t tok = (uint32_t)i >> 6, u = (uint32_t)i & 63;
        const void* src = g_xemb_bf + (size_t)(t0 + tok) * E + u * 8;
        uint32_t dst = sa + tok * 1024 + (((u & ~7u) | ((u ^ tok) & 7u)) << 4);
        CP_ASYNC16(dst, src);
    }
    // ---- B chunk 0
    const __nv_bfloat16* bbase = g_mk_bf + (size_t)n * MMEM * E;
    {
        for (int i = tid; i < 1024; i += 256) {
            uint32_t m = (uint32_t)i >> 3, u = (uint32_t)i & 7;
            const void* src = bbase + (size_t)m * E + u * 8;   // c=0, kc=0
            uint32_t dst = sa + SMEM_B_OFF + m * 128 + (((u ^ (m & 7u)) & 7u) << 4);
            CP_ASYNC16(dst, src);
        }
    }
    CP_COMMIT();

    float acc[2][8][4];
    #pragma unroll
    for (int mf = 0; mf < 2; mf++)
        #pragma unroll
        for (int nf = 0; nf < 8; nf++)
            #pragma unroll
            for (int r = 0; r < 4; r++) acc[mf][nf][r] = 0.f;

    // per-(thread,row) top-5 lists: list l covers row wm*32 + (l>>1)*16 + (l&1)*8 + (lane>>2)
    float tv[4][5]; int tix[4][5];
    #pragma unroll
    for (int l = 0; l < 4; l++)
        #pragma unroll
        for (int j = 0; j < 5; j++) { tv[l][j] = -1e30f; tix[l][j] = 0x7fffffff; }

    // per-lane address components
    uint32_t aTok0 = (uint32_t)(wm * 32) + (uint32_t)(lane & 15);   // mf=0 token row
    uint32_t aHi   = (uint32_t)(lane >> 4);                         // extra k-unit
    uint32_t bMemB = (uint32_t)(wn * 64) + ((uint32_t)(lane >> 4) << 3) + (uint32_t)(lane & 7);
    uint32_t bKHi  = (uint32_t)((lane >> 3) & 1);

    for (int f = 0; f < 128; f++) {             // f = chunk*8 + kc
        int kc = f & 7, buf = f & 1, c = f >> 3;
        CP_WAIT0();
        __syncthreads();
        if (f + 1 < 128) {
            int c2 = (f + 1) >> 3, kc2 = (f + 1) & 7, buf2 = (f + 1) & 1;
            const __nv_bfloat16* bsrc = bbase + (size_t)(c2 * 128) * E + kc2 * 64;
            uint32_t db = sa + SMEM_B_OFF + (uint32_t)buf2 * 16384u;
            for (int i = tid; i < 1024; i += 256) {
                uint32_t m = (uint32_t)i >> 3, u = (uint32_t)i & 7;
                CP_ASYNC16(db + m * 128 + (((u ^ (m & 7u)) & 7u) << 4),
                           bsrc + (size_t)m * E + u * 8);
            }
            CP_COMMIT();
        }

        // load A fragments for this k-chunk: 2 m-frags x 4 k-steps
        uint32_t a[2][4][4];
        #pragma unroll
        for (int mf = 0; mf < 2; mf++) {
            uint32_t tok = aTok0 + (uint32_t)(mf * 16);
            uint32_t rowb = sa + tok * 1024;
            #pragma unroll
            for (int ks = 0; ks < 4; ks++) {
                uint32_t u = (uint32_t)(kc * 8 + ks * 2) + aHi;
                uint32_t addr = rowb + (((u & ~7u) | ((u ^ tok) & 7u)) << 4);
                LDSM_X4(a[mf][ks][0], a[mf][ks][1], a[mf][ks][2], a[mf][ks][3], addr);
            }
        }
        uint32_t bB = sa + SMEM_B_OFF + (uint32_t)buf * 16384u;
        #pragma unroll
        for (int np = 0; np < 4; np++) {
            uint32_t mem = bMemB + (uint32_t)(np * 16);
            uint32_t rowb = bB + mem * 128;
            #pragma unroll
            for (int ks = 0; ks < 4; ks++) {
                uint32_t b0, b1, b2, b3;
                uint32_t u = (uint32_t)(ks * 2) + bKHi;
                uint32_t addr = rowb + (((u ^ (mem & 7u)) & 7u) << 4);
                LDSM_X4(b0, b1, b2, b3, addr);
                #pragma unroll
                for (int mf = 0; mf < 2; mf++) {
                    MMA16816(acc[mf][np * 2 + 0], a[mf][ks][0], a[mf][ks][1], a[mf][ks][2], a[mf][ks][3], b0, b1);
                    MMA16816(acc[mf][np * 2 + 1], a[mf][ks][0], a[mf][ks][1], a[mf][ks][2], a[mf][ks][3], b2, b3);
                }
            }
        }

        if (kc == 7) {  // fused screen epilogue: insert this chunk's 128 cols
            #pragma unroll
            for (int mf = 0; mf < 2; mf++) {
                #pragma unroll
                for (int nf = 0; nf < 8; nf++) {
                    int col = c * 128 + wn * 64 + nf * 8 + ((lane & 3) << 1);
                    upd5(tv[mf * 2 + 0], tix[mf * 2 + 0], acc[mf][nf][0], col, acc[mf][nf][1], col + 1);
                    upd5(tv[mf * 2 + 1], tix[mf * 2 + 1], acc[mf][nf][2], col, acc[mf][nf][3], col + 1);
                    acc[mf][nf][0] = acc[mf][nf][1] = acc[mf][nf][2] = acc[mf][nf][3] = 0.f;
                }
            }
        }
    }

    // ---- candidate merge: 8 threads x top-5 = 40 candidates per row
    __syncthreads();                      // all compute done; A region reusable
    float* cv = (float*)smem;             // 128 rows * 40 = 5120 floats (20 KB)
    int*   ci = (int*)(smem + 20480);     // 20 KB
    int slot = wn * 4 + (lane & 3);       // 0..7
    #pragma unroll
    for (int l = 0; l < 4; l++) {
        int row = wm * 32 + (l >> 1) * 16 + (l & 1) * 8 + (lane >> 2);
        int base = row * 40 + slot * 5;
        #pragma unroll
        for (int j = 0; j < 5; j++) { cv[base + j] = tv[l][j]; ci[base + j] = tix[l][j]; }
    }
    __syncthreads();
    if (tid < 128) {
        float v8[8]; int i8[8];
        #pragma unroll
        for (int j = 0; j < 8; j++) { v8[j] = -1e30f; i8[j] = 0x7fffffff; }
        int base = tid * 40;
        for (int j = 0; j < 40; j++) ins8(cv[base + j], ci[base + j], v8, i8);
        int gb = ((t0 + tid) * NSEC + n) * NCAND;
        #pragma unroll
        for (int j = 0; j < 8; j++) g_cand[gb + j] = i8[j];
    }
}

// ---------------------------------------------------------------------------
// K2c: exact fp32 rescore of 8 candidates -> exact top-4 + softmax weights
// ---------------------------------------------------------------------------
__global__ __launch_bounds__(256) void k2c_rescore(const float* __restrict__ mkeys) {
    int t = blockIdx.x;
    int tid = threadIdx.x, wid = tid >> 5, lane = tid & 31;
    __shared__ float xs[E];
    for (int e = tid; e < E; e += 256) xs[e] = g_xemb[(size_t)t * E + e];
    __syncthreads();

    int n  = wid;
    int cb = (t * NSEC + n) * NCAND;
    float sc[NCAND]; int id[NCAND];
    #pragma unroll
    for (int j = 0; j < NCAND; j++) {
        int mi = g_cand[cb + j];
        const float* kr = mkeys + ((size_t)n * MMEM + mi) * E;
        float acc = 0.f;
        for (int e = lane; e < E; e += 32) acc = fmaf(xs[e], kr[e], acc);
        #pragma unroll
        for (int o = 16; o > 0; o >>= 1) acc += __shfl_xor_sync(0xffffffffu, acc, o);
        sc[j] = acc; id[j] = mi;
    }
    if (lane == 0) {
        float v[4]; int ix[4];
        #pragma unroll
        for (int j = 0; j < 4; j++) { v[j] = -1e30f; ix[j] = 0x7fffffff; }
        #pragma unroll
        for (int j = 0; j < NCAND; j++) ins4tie(sc[j], id[j], v, ix);
        float e1 = expf(v[1] - v[0]);
        float e2 = expf(v[2] - v[0]);
        float e3 = expf(v[3] - v[0]);
        float inv = 1.f / (1.f + e1 + e2 + e3);
        int ob = (t * NSEC + n) * TOPK;
        g_tw[ob + 0] = inv;      g_tw[ob + 1] = e1 * inv;
        g_tw[ob + 2] = e2 * inv; g_tw[ob + 3] = e3 * inv;
        g_tidx[ob + 0] = ix[0];  g_tidx[ob + 1] = ix[1];
        g_tidx[ob + 2] = ix[2];  g_tidx[ob + 3] = ix[3];
    }
}

// ---------------------------------------------------------------------------
// K3: knowledge gather + combine + Wo proj + residual + layernorm
// ---------------------------------------------------------------------------
__global__ __launch_bounds__(256) void k3_out(
    const float* __restrict__ knowledge, const float* __restrict__ Wo,
    const float* __restrict__ bo, const float* __restrict__ gamma,
    const float* __restrict__ beta, const float* __restrict__ sector_dist,
    float* __restrict__ out)
{
    int t = blockIdx.x;
    int tid = threadIdx.x;
    int wid = tid >> 5, lane = tid & 31;
    __shared__ float qs[KD];
    __shared__ float ctxs[NSEC * VD];
    __shared__ float finals[VD];
    __shared__ float red[16];
    __shared__ float mu_s, rstd_s;

    if (tid < KD) qs[tid] = g_q[t * KD + tid];
    __syncthreads();

    {
        int n = wid;
        int base = (t * NSEC + n) * TOPK;
        float acc = 0.f;
        #pragma unroll
        for (int k = 0; k < TOPK; k++) {
            int   mi = g_tidx[base + k];
            float w  = g_tw[base + k];
            const float* A = knowledge + (size_t)(n * MMEM + mi) * (KD * VD);
            float p = 0.f;
            #pragma unroll
            for (int d = 0; d < KD; d++) p = fmaf(qs[d], A[d * VD + lane], p);
            acc = fmaf(w, p, acc);
        }
        acc *= sector_dist[t * NSEC + n];
        ctxs[n * VD + lane] = acc;
    }
    __syncthreads();
    if (tid < VD) {
        float f = 0.f;
        #pragma unroll
        for (int n = 0; n < NSEC; n++) f += ctxs[n * VD + tid];
        finals[tid] = f;
    }
    __syncthreads();

    int e0 = tid, e1 = tid + 256;
    float p0 = bo[e0], p1 = bo[e1];
    #pragma unroll
    for (int v = 0; v < VD; v++) {
        float fv = finals[v];
        p0 = fmaf(fv, Wo[v * E + e0], p0);
        p1 = fmaf(fv, Wo[v * E + e1], p1);
    }
    float h0 = g_xemb[(size_t)t * E + e0] + p0;
    float h1 = g_xemb[(size_t)t * E + e1] + p1;

    float s = h0 + h1, sq = h0 * h0 + h1 * h1;
    #pragma unroll
    for (int o = 16; o > 0; o >>= 1) {
        s  += __shfl_xor_sync(0xffffffffu, s,  o);
        sq += __shfl_xor_sync(0xffffffffu, sq, o);
    }
    if (lane == 0) { red[wid] = s; red[8 + wid] = sq; }
    __syncthreads();
    if (tid == 0) {
        float S = 0.f, SQ = 0.f;
        #pragma unroll
        for (int i = 0; i < 8; i++) { S += red[i]; SQ += red[8 + i]; }
        float mu  = S * (1.f / E);
        float var = SQ * (1.f / E) - mu * mu;
        mu_s = mu;
        rstd_s = 1.f / sqrtf(var + 1e-5f);
    }
    __syncthreads();
    out[(size_t)t * E + e0] = (h0 - mu_s) * rstd_s * gamma[e0] + beta[e0];
    out[(size_t)t * E + e1] = (h1 - mu_s) * rstd_s * gamma[e1] + beta[e1];
}

// ---------------------------------------------------------------------------
extern "C" void kernel_launch(void* const* d_in, const int* in_sizes, int n_in,
                              void* d_out, int out_size)
{
    int off = (n_in >= 2 && in_sizes[1] == 1) ? 1 : 0;
    const int*   x     = (const int*)  d_in[0];
    const float* emb   = (const float*)d_in[1 + off];
    const float* skeys = (const float*)d_in[2 + off];
    const float* mkeys = (const float*)d_in[3 + off];
    const float* knw   = (const float*)d_in[4 + off];
    const float* Wq    = (const float*)d_in[5 + off];
    const float* bq    = (const float*)d_in[6 + off];
    const float* Wo    = (const float*)d_in[7 + off];
    const float* bo    = (const float*)d_in[8 + off];
    const float* gamma = (const float*)d_in[9 + off];
    const float* beta  = (const float*)d_in[10 + off];

    float* out    = (float*)d_out;
    float* sector = out + (size_t)T_TOT * E;

    (void)cudaFuncSetAttribute(k2_gemm, cudaFuncAttributeMaxDynamicSharedMemorySize, K2_SMEM);

    kconv<<<4096, 256>>>(mkeys);
    k1_embed<<<T_TOT, 128>>>(x, emb, skeys, Wq, bq, sector);
    dim3 g2(T_TOT / 128, NSEC);
    k2_gemm<<<g2, 256, K2_SMEM>>>();
    k2c_rescore<<<T_TOT, 256>>>(mkeys);
    k3_out<<<T_TOT, 256>>>(knw, Wo, bo, gamma, beta, sector, out);
}